// round 17
// baseline (speedup 1.0000x reference)
#include <cuda_runtime.h>
#include <cuda_fp16.h>
#include <cstdint>

#define BB   2
#define NN   4096
#define DD   256
#define PC   320     // 3*64 (Wk) + 128 (W_lin)
#define DOUT 64

// ---------------- scratch ---------------------------------------------------
__device__ __half g_Kb[(size_t)BB * NN * NN];      // fp16 kernel matrices
__device__ __half g_Kw[(size_t)BB * NN * NN];
__device__ float  g_sq[BB * NN];
__device__ __half g_WcatT[(size_t)PC * DD];        // Wcat^T fp16 [c][d]
__device__ __half g_Xh[(size_t)BB * NN * DD];      // fp16 x
__device__ float  g_P[(size_t)BB * NN * PC];       // fp32 x@Wcat (cols 128-191 unused)
__device__ __half g_H2T[(size_t)BB * DOUT * NN];   // h2^T, fp16 [b][col][row]
__device__ __half g_tT[(size_t)4 * DOUT * NN];     // stage-1^T, fp16 [tb][col][row]
__device__ float  g_t0[(size_t)2 * BB * NN * DOUT];
__device__ float  g_t1[(size_t)2 * BB * NN * DOUT];
__device__ float  g_g0[(size_t)2 * BB * NN * DOUT];
__device__ float  g_g1[(size_t)2 * BB * NN * DOUT];

// ---------------- helpers ---------------------------------------------------
__device__ __forceinline__ void mma_f16(float c[4], const uint32_t a[4], const uint32_t b[2]) {
    asm volatile(
        "mma.sync.aligned.m16n8k16.row.col.f32.f16.f16.f32 "
        "{%0,%1,%2,%3}, {%4,%5,%6,%7}, {%8,%9}, {%0,%1,%2,%3};\n"
        : "+f"(c[0]), "+f"(c[1]), "+f"(c[2]), "+f"(c[3])
        : "r"(a[0]), "r"(a[1]), "r"(a[2]), "r"(a[3]),
          "r"(b[0]), "r"(b[1]));
}

__device__ __forceinline__ void ldsm_x4(uint32_t& r0, uint32_t& r1, uint32_t& r2, uint32_t& r3,
                                        uint32_t addr) {
    asm volatile("ldmatrix.sync.aligned.m8n8.x4.shared.b16 {%0,%1,%2,%3}, [%4];"
                 : "=r"(r0), "=r"(r1), "=r"(r2), "=r"(r3) : "r"(addr));
}

__device__ __forceinline__ void cpa16(uint32_t dst, const void* src) {
    asm volatile("cp.async.cg.shared.global [%0], [%1], 16;\n" :: "r"(dst), "l"(src));
}
#define CP_COMMIT() asm volatile("cp.async.commit_group;\n" ::: "memory")
#define CP_WAIT1()  asm volatile("cp.async.wait_group 1;\n" ::: "memory")

// Closed-form cubic B-spline on uniform knots {0,.25,.5,.75,1} (== reference).
__device__ __forceinline__ float b3fold(float v) {
    float outer = v * v * v * (1.f / 6.f);
    float inner = (((-3.f * v + 12.f) * v - 12.f) * v + 4.f) * (1.f / 6.f);
    return (v < 1.f) ? outer : inner;
}
__device__ __forceinline__ float bk_eval(float t) {
    float v = 2.f - fabsf(4.f * t - 2.f);
    return b3fold(v);
}
__device__ __forceinline__ float wk_eval(float t) {
    float sg = 8.f * t;
    bool lo = (sg < 4.f);
    float sp = lo ? sg : sg - 4.f;
    float v = 2.f - fabsf(sp - 2.f);
    float r = b3fold(v);
    return lo ? r : -r;
}

// ---------------- prep: fp16 convert + squared row norms (fused) -------------
// 8 warps/block, one row per warp. Each lane: 8 elements.
__global__ void k_prep(const float* __restrict__ x) {
    int row  = blockIdx.x * 8 + (threadIdx.x >> 5);
    int lane = threadIdx.x & 31;
    const float* xr = x + (size_t)row * DD + lane * 8;
    float4 v0 = *(const float4*)(xr);
    float4 v1 = *(const float4*)(xr + 4);
    float s = v0.x * v0.x + v0.y * v0.y + v0.z * v0.z + v0.w * v0.w
            + v1.x * v1.x + v1.y * v1.y + v1.z * v1.z + v1.w * v1.w;
    __half2 h0 = __floats2half2_rn(v0.x, v0.y);
    __half2 h1 = __floats2half2_rn(v0.z, v0.w);
    __half2 h2 = __floats2half2_rn(v1.x, v1.y);
    __half2 h3 = __floats2half2_rn(v1.z, v1.w);
    uint4 o;
    o.x = *(uint32_t*)&h0; o.y = *(uint32_t*)&h1;
    o.z = *(uint32_t*)&h2; o.w = *(uint32_t*)&h3;
    *(uint4*)(g_Xh + (size_t)row * DD + lane * 8) = o;
    #pragma unroll
    for (int o2 = 16; o2; o2 >>= 1) s += __shfl_xor_sync(0xffffffffu, s, o2);
    if (lane == 0) g_sq[row] = s;
}

__global__ void k_wcat(const float* __restrict__ Wk, const float* __restrict__ Wl) {
    int i = blockIdx.x * 256 + threadIdx.x;
    if (i >= DD * PC) return;
    int d = i / PC, cidx = i % PC;
    float v;
    if (cidx < 192) v = Wk[(size_t)(cidx / 64) * DD * 64 + (size_t)d * 64 + (cidx & 63)];
    else            v = Wl[(size_t)d * 128 + (cidx - 192)];
    g_WcatT[(size_t)cidx * DD + d] = __float2half_rn(v);
}

// ---------------- kernel: Gram + spline (fp16, ldmatrix, R15) ----------------
__global__ __launch_bounds__(256, 4) void k_gram() {
    __shared__ uint32_t sm[2 * 3840];
    int h   = blockIdx.x & 1;
    int idx = blockIdx.x >> 1;
    int b   = blockIdx.y;
    int tj = (int)((sqrtf(8.f * idx + 1.f) - 1.f) * 0.5f);
    while ((tj + 1) * (tj + 2) / 2 <= idx) ++tj;
    while (tj * (tj + 1) / 2 > idx) --tj;
    int ti = idx - tj * (tj + 1) / 2;

    int tid = threadIdx.x, lane = tid & 31, wid = tid >> 5;
    int wm = wid & 3, wn = wid >> 2;
    const __half* Xa = g_Xh + ((size_t)b * NN + (size_t)ti * 128) * DD;
    const __half* Xb = g_Xh + ((size_t)b * NN + (size_t)tj * 128 + (size_t)h * 64) * DD;
    uint32_t sb = (uint32_t)__cvta_generic_to_shared(sm);

    float c[2][4][4];
    #pragma unroll
    for (int i = 0; i < 2; i++)
        #pragma unroll
        for (int j = 0; j < 4; j++)
            #pragma unroll
            for (int r = 0; r < 4; r++) c[i][j][r] = 0.f;

    int arow_l = tid >> 2,         apart_l = tid & 3;
    int arow_h = (256 + tid) >> 2, apart_h = (256 + tid) & 3;
    int brow   = tid >> 2,         bpart   = tid & 3;

    uint32_t aRowOff = (uint32_t)(wm * 32 + (lane & 15)) * 80 + (uint32_t)(lane >> 4) * 16;
    uint32_t bRowOff = (uint32_t)(wn * 32 + ((lane >> 4) << 3) + (lane & 7)) * 80
                     + (uint32_t)((lane >> 3) & 1) * 16;

    {
        uint32_t sA = sb, sB = sb + 2560 * 4;
        cpa16(sA + (arow_l * 20 + apart_l * 4) * 4, Xa + (size_t)arow_l * DD + apart_l * 8);
        cpa16(sA + (arow_h * 20 + apart_h * 4) * 4, Xa + (size_t)arow_h * DD + apart_h * 8);
        cpa16(sB + (brow * 20 + bpart * 4) * 4, Xb + (size_t)brow * DD + bpart * 8);
    }
    CP_COMMIT();

    for (int cc = 0; cc < 8; ++cc) {
        if (cc + 1 < 8) {
            int s = (cc + 1) & 1, k0 = (cc + 1) * 32;
            uint32_t sA = sb + (s * 3840) * 4, sB = sA + 2560 * 4;
            cpa16(sA + (arow_l * 20 + apart_l * 4) * 4, Xa + (size_t)arow_l * DD + k0 + apart_l * 8);
            cpa16(sA + (arow_h * 20 + apart_h * 4) * 4, Xa + (size_t)arow_h * DD + k0 + apart_h * 8);
            cpa16(sB + (brow * 20 + bpart * 4) * 4, Xb + (size_t)brow * DD + k0 + bpart * 8);
        }
        CP_COMMIT();
        CP_WAIT1();
        __syncthreads();
        uint32_t As = sb + (cc & 1) * 3840 * 4;
        uint32_t Bs = As + 2560 * 4;
        #pragma unroll
        for (int ks = 0; ks < 2; ++ks) {
            uint32_t a[2][4], bf[4][2];
            #pragma unroll
            for (int mi = 0; mi < 2; mi++)
                ldsm_x4(a[mi][0], a[mi][1], a[mi][2], a[mi][3],
                        As + aRowOff + (uint32_t)mi * 16 * 80 + (uint32_t)ks * 32);
            ldsm_x4(bf[0][0], bf[0][1], bf[1][0], bf[1][1],
                    Bs + bRowOff + (uint32_t)ks * 32);
            ldsm_x4(bf[2][0], bf[2][1], bf[3][0], bf[3][1],
                    Bs + bRowOff + 16 * 80 + (uint32_t)ks * 32);
            #pragma unroll
            for (int mi = 0; mi < 2; mi++)
                #pragma unroll
                for (int ni = 0; ni < 4; ni++)
                    mma_f16(c[mi][ni], a[mi], bf[ni]);
        }
        __syncthreads();
    }

    __half* Kb = g_Kb + (size_t)b * NN * NN;
    __half* Kw = g_Kw + (size_t)b * NN * NN;
    const float* sq = g_sq + b * NN;
    int i0 = ti * 128 + wm * 32, j0 = tj * 128 + h * 64 + wn * 32;
    bool mir = (ti != tj);

    float sqi[2][2], sqj[4][2];
    #pragma unroll
    for (int mi = 0; mi < 2; mi++)
        #pragma unroll
        for (int rh = 0; rh < 2; rh++)
            sqi[mi][rh] = sq[i0 + mi * 16 + (lane >> 2) + rh * 8];
    #pragma unroll
    for (int ni = 0; ni < 4; ni++)
        #pragma unroll
        for (int rl = 0; rl < 2; rl++)
            sqj[ni][rl] = sq[j0 + ni * 8 + ((lane & 3) << 1) + rl];

    #pragma unroll
    for (int mi = 0; mi < 2; mi++)
        #pragma unroll
        for (int ni = 0; ni < 4; ni++)
            #pragma unroll
            for (int rh = 0; rh < 2; rh++) {
                int i = i0 + mi * 16 + (lane >> 2) + rh * 8;
                int j = j0 + ni * 8 + ((lane & 3) << 1);
                float bkv[2], wkv[2];
                #pragma unroll
                for (int rl = 0; rl < 2; rl++) {
                    float d2 = sqi[mi][rh] + sqj[ni][rl] - 2.f * c[mi][ni][rh * 2 + rl];
                    d2 = fmaxf(d2, 0.f);
                    float t = __expf(d2 * (-1.f / 512.f));
                    bkv[rl] = bk_eval(t);
                    wkv[rl] = wk_eval(t);
                }
                __half2 bh = __floats2half2_rn(bkv[0], bkv[1]);
                __half2 wh = __floats2half2_rn(wkv[0], wkv[1]);
                *(__half2*)(Kb + (size_t)i * NN + j) = bh;
                *(__half2*)(Kw + (size_t)i * NN + j) = wh;
                if (mir) {
                    Kb[(size_t)j * NN + i]       = __low2half(bh);
                    Kb[(size_t)(j + 1) * NN + i] = __high2half(bh);
                    Kw[(size_t)j * NN + i]       = __low2half(wh);
                    Kw[(size_t)(j + 1) * NN + i] = __high2half(wh);
                }
            }
}

// ---------------- kernel: projection (fp16, ldmatrix, ring; fused h2t) ------
// 64x64 tile; blockIdx.y==2 (cols 128..191) writes fp16 transposed to g_H2T.
__global__ __launch_bounds__(256, 4) void k_proj16() {
    __shared__ uint32_t sm[3 * 2560];
    int rt = blockIdx.x;
    int c0 = blockIdx.y * 64;
    const __half* Xa = g_Xh + (size_t)rt * 64 * DD;
    int tid = threadIdx.x, lane = tid & 31, wid = tid >> 5;
    int wm = wid & 3, wn = wid >> 2;
    uint32_t sb = (uint32_t)__cvta_generic_to_shared(sm);

    float c[4][4];
    #pragma unroll
    for (int i = 0; i < 4; i++)
        #pragma unroll
        for (int r = 0; r < 4; r++) c[i][r] = 0.f;

    int arow = tid >> 2, apart = tid & 3;
    uint32_t aRowOff = (uint32_t)(wm * 16 + (lane & 15)) * 80 + (uint32_t)(lane >> 4) * 16;
    uint32_t bRowOff = (uint32_t)(wn * 32 + ((lane >> 4) << 3) + (lane & 7)) * 80
                     + (uint32_t)((lane >> 3) & 1) * 16;

    const int NCH = 8;
    #pragma unroll
    for (int pc = 0; pc < 2; ++pc) {
        uint32_t sA = sb + pc * 2560 * 4, sB = sA + 1280 * 4;
        int k0 = pc * 32;
        cpa16(sA + (arow * 20 + apart * 4) * 4, Xa + (size_t)arow * DD + k0 + apart * 8);
        cpa16(sB + (arow * 20 + apart * 4) * 4, g_WcatT + (size_t)(c0 + arow) * DD + k0 + apart * 8);
        CP_COMMIT();
    }

    for (int cc = 0; cc < NCH; ++cc) {
        CP_WAIT1();
        __syncthreads();
        if (cc + 2 < NCH) {
            int st = (cc + 2) % 3, k0 = (cc + 2) * 32;
            uint32_t sA = sb + (st * 2560) * 4, sB = sA + 1280 * 4;
            cpa16(sA + (arow * 20 + apart * 4) * 4, Xa + (size_t)arow * DD + k0 + apart * 8);
            cpa16(sB + (arow * 20 + apart * 4) * 4, g_WcatT + (size_t)(c0 + arow) * DD + k0 + apart * 8);
        }
        CP_COMMIT();
        uint32_t As = sb + (uint32_t)(cc % 3) * 2560 * 4;
        uint32_t Bs = As + 1280 * 4;
        #pragma unroll
        for (int ks = 0; ks < 2; ++ks) {
            uint32_t a[4], bf[4][2];
            ldsm_x4(a[0], a[1], a[2], a[3], As + aRowOff + (uint32_t)ks * 32);
            ldsm_x4(bf[0][0], bf[0][1], bf[1][0], bf[1][1], Bs + bRowOff + (uint32_t)ks * 32);
            ldsm_x4(bf[2][0], bf[2][1], bf[3][0], bf[3][1], Bs + bRowOff + 16 * 80 + (uint32_t)ks * 32);
            #pragma unroll
            for (int ni = 0; ni < 4; ni++)
                mma_f16(c[ni], a, bf[ni]);
        }
    }

    if (c0 == 128) {
        // fused h2t: stage tile as fp16 in smem, write transposed to g_H2T
        __syncthreads();                      // all warps done reading pipeline smem
        __half* sh = (__half*)sm;             // [64][72]
        #pragma unroll
        for (int ni = 0; ni < 4; ni++)
            #pragma unroll
            for (int r = 0; r < 4; r++) {
                int row = wm * 16 + (lane >> 2) + ((r >> 1) << 3);
                int col = wn * 32 + ni * 8 + ((lane & 3) << 1) + (r & 1);
                sh[row * 72 + col] = __float2half_rn(c[ni][r]);
            }
        __syncthreads();
        int cT = tid >> 2, rq = (tid & 3) * 16;
        int b = (rt * 64) >> 12, n0 = (rt * 64) & (NN - 1);
        __half* dst = g_H2T + ((size_t)b * DOUT + cT) * NN + n0 + rq;
        #pragma unroll
        for (int q = 0; q < 16; ++q) dst[q] = sh[(rq + q) * 72 + cT];
    } else {
        #pragma unroll
        for (int ni = 0; ni < 4; ni++)
            #pragma unroll
            for (int r = 0; r < 4; r++) {
                int row = rt * 64 + wm * 16 + (lane >> 2) + ((r >> 1) << 3);
                int col = c0 + wn * 32 + ni * 8 + ((lane & 3) << 1) + (r & 1);
                g_P[(size_t)row * PC + col] = c[ni][r];
            }
    }
}

// ---------------- kernel: SpMM fp16, split-K x2, ldmatrix, 3-stage ring ------
__global__ __launch_bounds__(256, 4) void k_spmm16(int stage) {
    __shared__ uint32_t sm[3 * 2560];
    int rt = blockIdx.x, b = blockIdx.y;
    int type = blockIdx.z >> 1, sp = blockIdx.z & 1;
    int mbase = sp * (NN / 2);
    const __half* Km = (type ? g_Kw : g_Kb) + (size_t)b * NN * NN;
    const __half* Ht;
    float* Out;
    if (stage == 1) {
        Ht = g_H2T + (size_t)b * DOUT * NN;
        Out = (sp ? g_t1 : g_t0) + ((size_t)type * BB + b) * NN * DOUT;
    } else {
        Ht = g_tT + (size_t)(type * BB + b) * DOUT * NN;
        Out = (sp ? g_g1 : g_g0) + ((size_t)type * BB + b) * NN * DOUT;
    }
    int tid = threadIdx.x, lane = tid & 31, wid = tid >> 5;
    int wm = wid & 3, wn = wid >> 2;
    uint32_t sb = (uint32_t)__cvta_generic_to_shared(sm);

    float c[4][4];
    #pragma unroll
    for (int i = 0; i < 4; i++)
        #pragma unroll
        for (int r = 0; r < 4; r++) c[i][r] = 0.f;

    int arow = tid >> 2, apart = tid & 3;
    uint32_t aRowOff = (uint32_t)(wm * 16 + (lane & 15)) * 80 + (uint32_t)(lane >> 4) * 16;
    uint32_t bRowOff = (uint32_t)(wn * 32 + ((lane >> 4) << 3) + (lane & 7)) * 80
                     + (uint32_t)((lane >> 3) & 1) * 16;

    const int NCH = 64;    // 2048 / 32
    #pragma unroll
    for (int pc = 0; pc < 2; ++pc) {
        uint32_t sA = sb + pc * 2560 * 4, sB = sA + 1280 * 4;
        int m0 = mbase + pc * 32;
        cpa16(sA + (arow * 20 + apart * 4) * 4, Km + (size_t)(rt * 64 + arow) * NN + m0 + apart * 8);
        cpa16(sB + (arow * 20 + apart * 4) * 4, Ht + (size_t)arow * NN + m0 + apart * 8);
        CP_COMMIT();
    }

    #pragma unroll 1
    for (int cc = 0; cc < NCH; ++cc) {
        CP_WAIT1();
        __syncthreads();
        if (cc + 2 < NCH) {
            int st = (cc + 2) % 3, m0 = mbase + (cc + 2) * 32;
            uint32_t sA = sb + (st * 2560) * 4, sB = sA + 1280 * 4;
            cpa16(sA + (arow * 20 + apart * 4) * 4, Km + (size_t)(rt * 64 + arow) * NN + m0 + apart * 8);
            cpa16(sB + (arow * 20 + apart * 4) * 4, Ht + (size_t)arow * NN + m0 + apart * 8);
        }
        CP_COMMIT();
        uint32_t As = sb + (uint32_t)(cc % 3) * 2560 * 4;
        uint32_t Bs = As + 1280 * 4;
        #pragma unroll
        for (int ks = 0; ks < 2; ++ks) {
            uint32_t a[4], bf[4][2];
            ldsm_x4(a[0], a[1], a[2], a[3], As + aRowOff + (uint32_t)ks * 32);
            ldsm_x4(bf[0][0], bf[0][1], bf[1][0], bf[1][1], Bs + bRowOff + (uint32_t)ks * 32);
            ldsm_x4(bf[2][0], bf[2][1], bf[3][0], bf[3][1], Bs + bRowOff + 16 * 80 + (uint32_t)ks * 32);
            #pragma unroll
            for (int ni = 0; ni < 4; ni++)
                mma_f16(c[ni], a, bf[ni]);
        }
    }

    #pragma unroll
    for (int ni = 0; ni < 4; ni++)
        #pragma unroll
        for (int r = 0; r < 4; r++) {
            int row = rt * 64 + wm * 16 + (lane >> 2) + ((r >> 1) << 3);
            int col = wn * 32 + ni * 8 + ((lane & 3) << 1) + (r & 1);
            Out[(size_t)row * DOUT + col] = c[ni][r];
        }
}

// ---------------- combine stage-1 partials + h1, write fp16 transposed -------
__global__ __launch_bounds__(256) void k_comb1t() {
    __shared__ __half sh[64][72];
    int n0 = blockIdx.x * 64, tb = blockIdx.y;
    int b = tb & 1;
    int t = threadIdx.x;
    int r = t >> 2, cq = (t & 3) * 16;
    size_t base = ((size_t)tb * NN + n0 + r) * DOUT + cq;
    const float* P = g_P + ((size_t)b * NN + n0 + r) * PC + 64 + cq;
    #pragma unroll
    for (int q = 0; q < 4; ++q) {
        float4 v0 = *(const float4*)(g_t0 + base + q * 4);
        float4 v1 = *(const float4*)(g_t1 + base + q * 4);
        float4 vp = *(const float4*)(P + q * 4);
        sh[r][cq + q * 4 + 0] = __float2half_rn(v0.x + v1.x + vp.x);
        sh[r][cq + q * 4 + 1] = __float2half_rn(v0.y + v1.y + vp.y);
        sh[r][cq + q * 4 + 2] = __float2half_rn(v0.z + v1.z + vp.z);
        sh[r][cq + q * 4 + 3] = __float2half_rn(v0.w + v1.w + vp.w);
    }
    __syncthreads();
    int c = t >> 2, rq = (t & 3) * 16;
    __half* dst = g_tT + ((size_t)tb * DOUT + c) * NN + n0 + rq;
    #pragma unroll
    for (int q = 0; q < 16; ++q) dst[q] = sh[rq + q][c];
}

// ---------------- final epilogue ---------------------------------------------
__global__ void k_final(const float* __restrict__ b_lin, float* __restrict__ out) {
    int idx = blockIdx.x * 256 + threadIdx.x;
    int cidx = idx & 127;
    int n = (idx >> 7) & (NN - 1);
    int b = idx >> 19;
    int half = cidx >> 6, cc = cidx & 63;
    const float* P = g_P + ((size_t)b * NN + n) * PC;
    size_t gi = (((size_t)half * BB + b) * NN + n) * DOUT + cc;
    float g = g_g0[gi] + g_g1[gi];
    float v = P[cc] + g + P[192 + cidx] + b_lin[cidx];
    out[idx] = fmaxf(v, 0.f);
}

// ---------------- launch -----------------------------------------------------
extern "C" void kernel_launch(void* const* d_in, const int* in_sizes, int n_in,
                              void* d_out, int out_size) {
    const float* x  = (const float*)d_in[0];
    const float* Wk = (const float*)d_in[1];
    const float* Wl = (const float*)d_in[2];
    const float* bl = (const float*)d_in[3];
    float* out = (float*)d_out;

    k_prep<<<BB * NN / 8, 256>>>(x);
    k_wcat<<<(DD * PC + 255) / 256, 256>>>(Wk, Wl);
    k_gram<<<dim3(1056, BB), 256>>>();
    k_proj16<<<dim3((BB * NN) / 64, PC / 64), 256>>>();
    k_spmm16<<<dim3(NN / 64, BB, 4), 256>>>(1);
    k_comb1t<<<dim3(NN / 64, 4), 256>>>();
    k_spmm16<<<dim3(NN / 64, BB, 4), 256>>>(2);
    k_final<<<(BB * NN * 128) / 256, 256>>>(bl, out);
}